// round 6
// baseline (speedup 1.0000x reference)
#include <cuda_runtime.h>
#include <cstdint>

// ---------------------------------------------------------------------------
// Swin window-MSA, fp32, FFMA2 (fma.rn.f32x2) packed along the K dimension so
// that float4 loads yield ready-made 64-bit operand pairs (no ALU packing).
//   B=64, L=3136 (56x56), C=96, H=3, E=32, window 7x7 (49 tokens)
// ---------------------------------------------------------------------------

#define BATCH   64
#define IMG     56
#define WINSZ   7
#define NWIN    8
#define TOK     49
#define HEADS   3
#define CDIM    96
#define EDIM    32
#define LDIM    3136
#define MROWS   200704
#define WTOT    12288

typedef unsigned long long u64;

__device__ __align__(16) float g_Q[WTOT * TOK * EDIM];
__device__ __align__(16) float g_K[WTOT * TOK * EDIM];
__device__ __align__(16) float g_V[WTOT * TOK * EDIM];
__device__ __align__(16) float g_AO[MROWS * CDIM];

// ---- packed f32x2 helpers ----
__device__ __forceinline__ u64 pack2(float a, float b) {
    u64 r;
    asm("mov.b64 %0, {%1, %2};" : "=l"(r) : "f"(a), "f"(b));
    return r;
}
__device__ __forceinline__ u64 fma2(u64 a, u64 b, u64 c) {
    u64 d;
    asm("fma.rn.f32x2 %0, %1, %2, %3;" : "=l"(d) : "l"(a), "l"(b), "l"(c));
    return d;
}
__device__ __forceinline__ float2 unpack2(u64 v) {
    float2 f;
    asm("mov.b64 {%0, %1}, %2;" : "=f"(f.x), "=f"(f.y) : "l"(v));
    return f;
}
__device__ __forceinline__ float hsum2(u64 v) {
    float2 f = unpack2(v);
    return f.x + f.y;
}

// ---------------------------------------------------------------------------
// Kernel 1: QKV GEMM + window scatter.
// grid (1568, 3) = 128-row tile x head, block 256.
// Thread (e = lane, rg = warp): 16 rows (two passes of 8).
// Accumulators hold k-pair partial sums; bias seeded into lane 0.
// ---------------------------------------------------------------------------
__global__ void __launch_bounds__(256) qkv_kernel(
    const float* __restrict__ x,
    const float* __restrict__ wqkv,
    const float* __restrict__ bqkv)
{
    __shared__ __align__(16) float wq[32 * 100];
    __shared__ __align__(16) float wk[32 * 100];
    __shared__ __align__(16) float wv[32 * 100];
    __shared__ int rowdst[128];

    const int tile = blockIdx.x;
    const int h    = blockIdx.y;
    const int tid  = threadIdx.x;

    // weight panel transposed: wq[e][k] = wqkv[k][h*96 + 3e + 0], etc.
    for (int t = tid; t < 96 * 96; t += 256) {
        int k = t / 96, j = t - k * 96;
        float val = wqkv[k * 288 + h * 96 + j];
        int e = j / 3, kk = j - e * 3;
        float* dst = (kk == 0) ? wq : (kk == 1) ? wk : wv;
        dst[e * 100 + k] = val;
    }
    if (tid < 128) {
        int gr  = tile * 128 + tid;
        int b   = gr / LDIM;
        int pix = gr - b * LDIM;
        int yy  = pix / IMG, xx = pix - yy * IMG;
        int win = (yy / WINSZ) * NWIN + (xx / WINSZ);
        int tok = (yy % WINSZ) * WINSZ + (xx % WINSZ);
        rowdst[tid] = (((b * HEADS + h) * (NWIN * NWIN) + win) * TOK + tok) * EDIM;
    }
    __syncthreads();

    const int e  = tid & 31;
    const int rg = tid >> 5;
    const float bq = bqkv[h * 96 + e * 3 + 0];
    const float bk = bqkv[h * 96 + e * 3 + 1];
    const float bv = bqkv[h * 96 + e * 3 + 2];

    #pragma unroll
    for (int pass = 0; pass < 2; pass++) {
        const int r0 = rg * 16 + pass * 8;
        const float* xb = x + ((size_t)tile * 128 + r0) * 96;

        u64 aq[8], ak[8], av[8];
        #pragma unroll
        for (int r = 0; r < 8; r++) {
            aq[r] = pack2(bq, 0.f);
            ak[r] = pack2(bk, 0.f);
            av[r] = pack2(bv, 0.f);
        }

        #pragma unroll 2
        for (int k4 = 0; k4 < 24; k4++) {
            ulonglong2 x2[8];
            #pragma unroll
            for (int r = 0; r < 8; r++)
                x2[r] = *(const ulonglong2*)(xb + (size_t)r * 96 + k4 * 4);
            ulonglong2 wq2 = *(const ulonglong2*)&wq[e * 100 + k4 * 4];
            ulonglong2 wk2 = *(const ulonglong2*)&wk[e * 100 + k4 * 4];
            ulonglong2 wv2 = *(const ulonglong2*)&wv[e * 100 + k4 * 4];
            #pragma unroll
            for (int r = 0; r < 8; r++) {
                aq[r] = fma2(x2[r].x, wq2.x, aq[r]);
                aq[r] = fma2(x2[r].y, wq2.y, aq[r]);
                ak[r] = fma2(x2[r].x, wk2.x, ak[r]);
                ak[r] = fma2(x2[r].y, wk2.y, ak[r]);
                av[r] = fma2(x2[r].x, wv2.x, av[r]);
                av[r] = fma2(x2[r].y, wv2.y, av[r]);
            }
        }

        #pragma unroll
        for (int r = 0; r < 8; r++) {
            int d = rowdst[r0 + r] + e;
            g_Q[d] = hsum2(aq[r]);
            g_K[d] = hsum2(ak[r]);
            g_V[d] = hsum2(av[r]);
        }
    }
}

// ---------------------------------------------------------------------------
// Kernel 2: per-window attention.  grid 12288, block 64 (threads 0..48 own a
// query row).  Scores and PV both use FFMA2 over E-pairs.
// ---------------------------------------------------------------------------
__global__ void __launch_bounds__(64) attn_kernel(const float* __restrict__ rel_bias)
{
    __shared__ __align__(16) float4 Ks4[392];   // 49*32 floats
    __shared__ __align__(16) float4 Vs4[392];
    __shared__ float  Bs[TOK * TOK];

    const int widx = blockIdx.x;
    const int tid  = threadIdx.x;

    const float* kb = g_K + (size_t)widx * (TOK * EDIM);
    const float* vb = g_V + (size_t)widx * (TOK * EDIM);
    for (int i = tid; i < 392; i += 64) {
        Ks4[i] = ((const float4*)kb)[i];
        Vs4[i] = ((const float4*)vb)[i];
    }
    for (int i = tid; i < TOK * TOK; i += 64) Bs[i] = rel_bias[i];
    __syncthreads();

    if (tid < TOK) {
        const float* qb = g_Q + (size_t)widx * (TOK * EDIM) + tid * EDIM;
        u64 qq[16];
        #pragma unroll
        for (int p = 0; p < 8; p++) {
            ulonglong2 qv = ((const ulonglong2*)qb)[p];
            qq[2 * p] = qv.x; qq[2 * p + 1] = qv.y;
        }

        const float scale = 0.17677669529663687f;  // 1/sqrt(32)
        const float* Ks = (const float*)Ks4;
        const float* Vs = (const float*)Vs4;

        float s[TOK];
        float mx = -1e30f;
        #pragma unroll 7
        for (int j = 0; j < TOK; j++) {
            const ulonglong2* kr = (const ulonglong2*)(Ks + j * EDIM);
            u64 acc = 0ull;  // (0.f, 0.f)
            #pragma unroll
            for (int p = 0; p < 8; p++) {
                ulonglong2 kv = kr[p];
                acc = fma2(qq[2 * p], kv.x, acc);
                acc = fma2(qq[2 * p + 1], kv.y, acc);
            }
            float d = hsum2(acc) * scale + Bs[tid * TOK + j];
            s[j] = d;
            mx = fmaxf(mx, d);
        }
        float sum = 0.f;
        #pragma unroll
        for (int j = 0; j < TOK; j++) {
            s[j] = __expf(s[j] - mx);
            sum += s[j];
        }
        float inv = 1.0f / sum;

        u64 oo[16];
        #pragma unroll
        for (int p = 0; p < 16; p++) oo[p] = 0ull;
        #pragma unroll 7
        for (int j = 0; j < TOK; j++) {
            float p = s[j] * inv;
            u64 pd = pack2(p, p);
            const ulonglong2* vr = (const ulonglong2*)(Vs + j * EDIM);
            #pragma unroll
            for (int t = 0; t < 8; t++) {
                ulonglong2 vv = vr[t];
                oo[2 * t]     = fma2(pd, vv.x, oo[2 * t]);
                oo[2 * t + 1] = fma2(pd, vv.y, oo[2 * t + 1]);
            }
        }

        int b   = widx / (HEADS * NWIN * NWIN);
        int rem = widx - b * (HEADS * NWIN * NWIN);
        int h   = rem / (NWIN * NWIN);
        int win = rem - h * (NWIN * NWIN);
        int yy  = (win / NWIN) * WINSZ + tid / WINSZ;
        int xx  = (win % NWIN) * WINSZ + tid % WINSZ;
        float* dst = g_AO + ((size_t)b * LDIM + yy * IMG + xx) * CDIM + h * EDIM;
        #pragma unroll
        for (int t = 0; t < 8; t++) {
            float2 lo = unpack2(oo[2 * t]);
            float2 hi = unpack2(oo[2 * t + 1]);
            ((float4*)dst)[t] = make_float4(lo.x, lo.y, hi.x, hi.y);
        }
    }
}

// ---------------------------------------------------------------------------
// Kernel 3: output projection GEMM.  grid 1568, block 256.
// Thread (e, rg): columns {e, e+32, e+64}, 16 rows (two passes of 8),
// k-pair FFMA2.  Writes coalesced.
// ---------------------------------------------------------------------------
__global__ void __launch_bounds__(256) proj_kernel(
    const float* __restrict__ wproj,
    const float* __restrict__ bproj,
    float* __restrict__ out)
{
    __shared__ __align__(16) float w0s[32 * 100];
    __shared__ __align__(16) float w1s[32 * 100];
    __shared__ __align__(16) float w2s[32 * 100];

    const int tile = blockIdx.x;
    const int tid  = threadIdx.x;

    // wjs[e][k] = wproj[k][32*j + e]
    for (int t = tid; t < 96 * 96; t += 256) {
        int k = t / 96, c = t - k * 96;
        int j = c >> 5, e2 = c & 31;
        float* dst = (j == 0) ? w0s : (j == 1) ? w1s : w2s;
        dst[e2 * 100 + k] = wproj[t];
    }
    __syncthreads();

    const int e  = tid & 31;
    const int rg = tid >> 5;
    const float b0 = bproj[e];
    const float b1 = bproj[32 + e];
    const float b2 = bproj[64 + e];

    #pragma unroll
    for (int pass = 0; pass < 2; pass++) {
        const int r0 = rg * 16 + pass * 8;
        const float* xb = g_AO + ((size_t)tile * 128 + r0) * 96;

        u64 a0[8], a1[8], a2[8];
        #pragma unroll
        for (int r = 0; r < 8; r++) {
            a0[r] = pack2(b0, 0.f);
            a1[r] = pack2(b1, 0.f);
            a2[r] = pack2(b2, 0.f);
        }

        #pragma unroll 2
        for (int k4 = 0; k4 < 24; k4++) {
            ulonglong2 x2[8];
            #pragma unroll
            for (int r = 0; r < 8; r++)
                x2[r] = *(const ulonglong2*)(xb + (size_t)r * 96 + k4 * 4);
            ulonglong2 w02 = *(const ulonglong2*)&w0s[e * 100 + k4 * 4];
            ulonglong2 w12 = *(const ulonglong2*)&w1s[e * 100 + k4 * 4];
            ulonglong2 w22 = *(const ulonglong2*)&w2s[e * 100 + k4 * 4];
            #pragma unroll
            for (int r = 0; r < 8; r++) {
                a0[r] = fma2(x2[r].x, w02.x, a0[r]);
                a0[r] = fma2(x2[r].y, w02.y, a0[r]);
                a1[r] = fma2(x2[r].x, w12.x, a1[r]);
                a1[r] = fma2(x2[r].y, w12.y, a1[r]);
                a2[r] = fma2(x2[r].x, w22.x, a2[r]);
                a2[r] = fma2(x2[r].y, w22.y, a2[r]);
            }
        }

        float* ob = out + ((size_t)tile * 128 + r0) * 96;
        #pragma unroll
        for (int r = 0; r < 8; r++) {
            int o = r * 96;
            ob[o + e]      = hsum2(a0[r]);
            ob[o + 32 + e] = hsum2(a1[r]);
            ob[o + 64 + e] = hsum2(a2[r]);
        }
    }
}

// ---------------------------------------------------------------------------
extern "C" void kernel_launch(void* const* d_in, const int* in_sizes, int n_in,
                              void* d_out, int out_size)
{
    (void)in_sizes; (void)n_in; (void)out_size;
    const float* x        = (const float*)d_in[0];
    const float* w_qkv    = (const float*)d_in[1];
    const float* b_qkv    = (const float*)d_in[2];
    const float* w_proj   = (const float*)d_in[3];
    const float* b_proj   = (const float*)d_in[4];
    const float* rel_bias = (const float*)d_in[5];
    float* out = (float*)d_out;

    qkv_kernel<<<dim3(1568, 3), 256>>>(x, w_qkv, b_qkv);
    attn_kernel<<<WTOT, 64>>>(rel_bias);
    proj_kernel<<<1568, 256>>>(w_proj, b_proj, out);
}